// round 1
// baseline (speedup 1.0000x reference)
#include <cuda_runtime.h>
#include <math.h>

#define BB 8
#define DD 512
#define LL 2048
#define HH 8
#define DHH 64
#define OT 1536        // fused output cols: [0,512)=K, [512,1024)=V, [1024,1536)=Q(scaled)
#define SSTR 68        // padded smem row stride (floats), multiple of 4 for float4

// Scratch: (B, L, 1536) fp32 = 100.7 MB. Static device global (no runtime alloc).
__device__ float g_kvq[(size_t)BB * LL * OT];

// ---------------------------------------------------------------------------
// Projection GEMM: g_kvq[b][l][o] = sum_d W[o][d] * queries[b][d][l]
//   o <  1024 : w_mem row o          (K for o<512, V for 512<=o<1024)
//   o >= 1024 : w_q row (o-1024), scaled by DH^-0.5 = 0.125
// Tile: 128(l) x 128(o) x 8(d), 256 threads, 8x8 per-thread.
// ---------------------------------------------------------------------------
__global__ __launch_bounds__(256) void proj_kernel(
    const float* __restrict__ qin,
    const float* __restrict__ w_mem,
    const float* __restrict__ w_q)
{
    __shared__ float As[8][128];   // As[d][l]  (queries slab: l-contiguous)
    __shared__ float Bs[8][128];   // Bs[d][o]  (weights, transposed on load)

    const int b  = blockIdx.z;
    const int l0 = blockIdx.x * 128;
    const int o0 = blockIdx.y * 128;
    const int t  = threadIdx.x;
    const int ty = t >> 4, tx = t & 15;

    const float* wptr = (o0 < 1024) ? (w_mem + (size_t)o0 * DD)
                                    : (w_q  + (size_t)(o0 - 1024) * DD);
    const float* qb = qin + (size_t)b * DD * LL;

    float c[8][8];
    #pragma unroll
    for (int i = 0; i < 8; i++)
        #pragma unroll
        for (int j = 0; j < 8; j++) c[i][j] = 0.f;

    const int ak = t >> 5, am = (t & 31) << 2;   // A load: row ak (d), col am (l)
    const int bn = t >> 1, bk = (t & 1) << 2;    // B load: row bn (o), col bk (d)

    for (int d0 = 0; d0 < DD; d0 += 8) {
        float4 av = *(const float4*)(qb + (size_t)(d0 + ak) * LL + l0 + am);
        float4 bv = *(const float4*)(wptr + (size_t)bn * DD + d0 + bk);
        __syncthreads();
        *(float4*)&As[ak][am] = av;
        Bs[bk + 0][bn] = bv.x;
        Bs[bk + 1][bn] = bv.y;
        Bs[bk + 2][bn] = bv.z;
        Bs[bk + 3][bn] = bv.w;
        __syncthreads();
        #pragma unroll
        for (int kk = 0; kk < 8; kk++) {
            float a[8], bb2[8];
            *(float4*)&a[0]   = *(float4*)&As[kk][ty * 8];
            *(float4*)&a[4]   = *(float4*)&As[kk][ty * 8 + 4];
            *(float4*)&bb2[0] = *(float4*)&Bs[kk][tx * 8];
            *(float4*)&bb2[4] = *(float4*)&Bs[kk][tx * 8 + 4];
            #pragma unroll
            for (int i = 0; i < 8; i++)
                #pragma unroll
                for (int j = 0; j < 8; j++)
                    c[i][j] += a[i] * bb2[j];
        }
    }

    const float scale = (o0 >= 1024) ? 0.125f : 1.0f;
    float* outp = g_kvq + (size_t)b * LL * OT;
    #pragma unroll
    for (int i = 0; i < 8; i++) {
        size_t row = (size_t)(l0 + ty * 8 + i) * OT + o0 + tx * 8;
        float4 v0 = make_float4(c[i][0] * scale, c[i][1] * scale,
                                c[i][2] * scale, c[i][3] * scale);
        float4 v1 = make_float4(c[i][4] * scale, c[i][5] * scale,
                                c[i][6] * scale, c[i][7] * scale);
        *(float4*)(outp + row)     = v0;
        *(float4*)(outp + row + 4) = v1;
    }
}

// ---------------------------------------------------------------------------
// Flash attention: per block (b, h, 64-row q tile). 256 threads = 16x16,
// each thread owns a 4(q) x 4(k or dh) micro-tile. Online softmax with
// exact reference mask semantics (masked logits = -1e30).
// ---------------------------------------------------------------------------
__global__ __launch_bounds__(256) void attn_kernel(
    const int* __restrict__ mask, float* __restrict__ out)
{
    extern __shared__ float sm[];
    float* QsT = sm;                  // [64 dh][SSTR]  (dh-major, qi cols)
    float* KsT = sm + 64 * SSTR;      // [64 dh][SSTR]  (dh-major, kj cols)
    float* Vs  = sm + 2 * 64 * SSTR;  // [64 kj][SSTR]  (kj-major, dh cols)
    float* Ps  = sm + 3 * 64 * SSTR;  // [64 qi][SSTR]  (P tile / epilogue staging)
    float* Ms  = sm + 4 * 64 * SSTR;  // [64] mask values

    const int b  = blockIdx.z;
    const int h  = blockIdx.y;
    const int q0 = blockIdx.x * 64;
    const int t  = threadIdx.x;
    const int ty = t >> 4, tx = t & 15;

    const float* base = g_kvq + (size_t)b * LL * OT + h * 64;
    const float* Kg = base;
    const float* Vg = base + 512;
    const float* Qg = base + 1024;

    const int r0  = (t >> 4) << 2;    // 4 consecutive rows per thread
    const int dh4 = (t & 15) << 2;    // 4 consecutive dh per thread

    // Load Q tile transposed: QsT[dh][qi]
    {
        float vv[4][4];
        #pragma unroll
        for (int r = 0; r < 4; r++) {
            float4 u = *(const float4*)(Qg + (size_t)(q0 + r0 + r) * OT + dh4);
            vv[r][0] = u.x; vv[r][1] = u.y; vv[r][2] = u.z; vv[r][3] = u.w;
        }
        #pragma unroll
        for (int i = 0; i < 4; i++)
            *(float4*)&QsT[(dh4 + i) * SSTR + r0] =
                make_float4(vv[0][i], vv[1][i], vv[2][i], vv[3][i]);
    }

    float acc[4][4];
    float mrow[4], lrow[4];
    #pragma unroll
    for (int i = 0; i < 4; i++) {
        mrow[i] = -INFINITY;
        lrow[i] = 0.f;
        #pragma unroll
        for (int j = 0; j < 4; j++) acc[i][j] = 0.f;
    }

    for (int k0 = 0; k0 < LL; k0 += 64) {
        __syncthreads();   // previous iteration's smem reads are done
        // Load K (transposed) + V (direct) + mask
        {
            float kvv[4][4];
            #pragma unroll
            for (int r = 0; r < 4; r++) {
                float4 u = *(const float4*)(Kg + (size_t)(k0 + r0 + r) * OT + dh4);
                kvv[r][0] = u.x; kvv[r][1] = u.y; kvv[r][2] = u.z; kvv[r][3] = u.w;
                float4 w2 = *(const float4*)(Vg + (size_t)(k0 + r0 + r) * OT + dh4);
                *(float4*)&Vs[(r0 + r) * SSTR + dh4] = w2;
            }
            #pragma unroll
            for (int i = 0; i < 4; i++)
                *(float4*)&KsT[(dh4 + i) * SSTR + r0] =
                    make_float4(kvv[0][i], kvv[1][i], kvv[2][i], kvv[3][i]);
            if (t < 64) Ms[t] = (float)mask[(size_t)b * LL + k0 + t];
        }
        __syncthreads();

        // S = Q @ K^T  (64x64, outer product over dh)
        float s[4][4];
        #pragma unroll
        for (int i = 0; i < 4; i++)
            #pragma unroll
            for (int j = 0; j < 4; j++) s[i][j] = 0.f;

        #pragma unroll 8
        for (int dh = 0; dh < 64; dh++) {
            float4 a  = *(float4*)&QsT[dh * SSTR + ty * 4];
            float4 kq = *(float4*)&KsT[dh * SSTR + tx * 4];
            float aa[4] = {a.x, a.y, a.z, a.w};
            float kk[4] = {kq.x, kq.y, kq.z, kq.w};
            #pragma unroll
            for (int i = 0; i < 4; i++)
                #pragma unroll
                for (int j = 0; j < 4; j++)
                    s[i][j] += aa[i] * kk[j];
        }

        // Mask + online softmax (row reductions over the 16 tx lanes)
        #pragma unroll
        for (int i = 0; i < 4; i++) {
            #pragma unroll
            for (int j = 0; j < 4; j++) {
                float mj = Ms[tx * 4 + j];
                s[i][j] = (mj > 0.5f) ? s[i][j] : -1e30f;
            }
            float mx = fmaxf(fmaxf(s[i][0], s[i][1]), fmaxf(s[i][2], s[i][3]));
            #pragma unroll
            for (int off = 1; off < 16; off <<= 1)
                mx = fmaxf(mx, __shfl_xor_sync(0xffffffffu, mx, off));
            float mnew = fmaxf(mrow[i], mx);
            float sc = __expf(mrow[i] - mnew);
            float rs = 0.f;
            #pragma unroll
            for (int j = 0; j < 4; j++) {
                float p = __expf(s[i][j] - mnew);
                s[i][j] = p;
                rs += p;
            }
            #pragma unroll
            for (int off = 1; off < 16; off <<= 1)
                rs += __shfl_xor_sync(0xffffffffu, rs, off);
            lrow[i] = lrow[i] * sc + rs;
            mrow[i] = mnew;
            #pragma unroll
            for (int j = 0; j < 4; j++) acc[i][j] *= sc;
            *(float4*)&Ps[(ty * 4 + i) * SSTR + tx * 4] =
                make_float4(s[i][0], s[i][1], s[i][2], s[i][3]);
        }
        __syncthreads();

        // O += P @ V  (outer product over kj; Ps column reads broadcast per warp)
        #pragma unroll 8
        for (int kj = 0; kj < 64; kj++) {
            float4 vv4 = *(float4*)&Vs[kj * SSTR + tx * 4];
            #pragma unroll
            for (int i = 0; i < 4; i++) {
                float p = Ps[(ty * 4 + i) * SSTR + kj];
                acc[i][0] += p * vv4.x;
                acc[i][1] += p * vv4.y;
                acc[i][2] += p * vv4.z;
                acc[i][3] += p * vv4.w;
            }
        }
    }

    // Epilogue: normalize, transpose through smem, coalesced store to (B,D,L)
    __syncthreads();
    #pragma unroll
    for (int i = 0; i < 4; i++) {
        float inv = 1.0f / lrow[i];
        #pragma unroll
        for (int j = 0; j < 4; j++)
            Ps[(tx * 4 + j) * SSTR + ty * 4 + i] = acc[i][j] * inv;
    }
    __syncthreads();
    {
        const int dh = t >> 2;
        const int qq = (t & 3) << 4;
        float* op = out + ((size_t)b * DD + h * 64 + dh) * LL + q0 + qq;
        #pragma unroll
        for (int r = 0; r < 4; r++)
            *(float4*)(op + r * 4) = *(float4*)&Ps[dh * SSTR + qq + r * 4];
    }
}

// ---------------------------------------------------------------------------
extern "C" void kernel_launch(void* const* d_in, const int* in_sizes, int n_in,
                              void* d_out, int out_size) {
    const float* queries = (const float*)d_in[0];
    const int*   mask    = (const int*)d_in[1];
    const float* w_mem   = (const float*)d_in[2];
    const float* w_q     = (const float*)d_in[3];
    float* out = (float*)d_out;

    dim3 gp(LL / 128, OT / 128, BB);          // 16 x 12 x 8 = 1536 blocks
    proj_kernel<<<gp, 256>>>(queries, w_mem, w_q);

    const int smem_bytes = (4 * 64 * SSTR + 64) * (int)sizeof(float);  // ~69.9 KB
    cudaFuncSetAttribute(attn_kernel,
                         cudaFuncAttributeMaxDynamicSharedMemorySize, smem_bytes);
    dim3 ga(LL / 64, HH, BB);                 // 32 x 8 x 8 = 2048 blocks
    attn_kernel<<<ga, 256, smem_bytes>>>(mask, out);
}

// round 4
// speedup vs baseline: 3.3494x; 3.3494x over previous
#include <cuda_runtime.h>
#include <cuda_bf16.h>
#include <cstdint>
#include <math.h>

#define BB 8
#define DD 512
#define LL 2048
#define HH 8
#define OT 1536        // fused proj cols: [0,512)=K, [512,1024)=V, [1024,1536)=Q(scaled)

// fp32 scratch: proj output (100.7MB) + V transposed (33.6MB)
__device__ float g_kvq[(size_t)BB * LL * OT];
__device__ float g_vt[(size_t)BB * DD * LL];

// ============================ helpers ======================================
__device__ __forceinline__ uint32_t smem_u32(const void* p) {
    uint32_t a;
    asm("{ .reg .u64 t; cvta.to.shared.u64 t, %1; cvt.u32.u64 %0, t; }"
        : "=r"(a) : "l"(p));
    return a;
}

#define SWZ128(off) ((off) ^ (((off) >> 3) & 0x70))

__device__ __forceinline__ void ldsm4(uint32_t* r, uint32_t addr) {
    asm volatile("ldmatrix.sync.aligned.m8n8.x4.shared.b16 {%0,%1,%2,%3}, [%4];"
        : "=r"(r[0]), "=r"(r[1]), "=r"(r[2]), "=r"(r[3]) : "r"(addr));
}

__device__ __forceinline__ void mma16816(float* d, const uint32_t* a, const uint32_t* b) {
    asm volatile("mma.sync.aligned.m16n8k16.row.col.f32.bf16.bf16.f32 "
        "{%0,%1,%2,%3}, {%4,%5,%6,%7}, {%8,%9}, {%0,%1,%2,%3};"
        : "+f"(d[0]), "+f"(d[1]), "+f"(d[2]), "+f"(d[3])
        : "r"(a[0]), "r"(a[1]), "r"(a[2]), "r"(a[3]), "r"(b[0]), "r"(b[1]));
}

// split fp32x4 -> bf16 hi/lo pairs, store swizzled (byte_off within tile)
__device__ __forceinline__ void cvt_store4(char* smem, uint32_t hi_off, uint32_t lo_off,
                                           uint32_t byte_off, float4 v) {
    __nv_bfloat162 h0, h1, l0, l1;
    h0.x = __float2bfloat16_rn(v.x); h0.y = __float2bfloat16_rn(v.y);
    h1.x = __float2bfloat16_rn(v.z); h1.y = __float2bfloat16_rn(v.w);
    l0.x = __float2bfloat16_rn(v.x - __bfloat162float(h0.x));
    l0.y = __float2bfloat16_rn(v.y - __bfloat162float(h0.y));
    l1.x = __float2bfloat16_rn(v.z - __bfloat162float(h1.x));
    l1.y = __float2bfloat16_rn(v.w - __bfloat162float(h1.y));
    uint32_t s = SWZ128(byte_off);
    *(__nv_bfloat162*)(smem + hi_off + s)     = h0;
    *(__nv_bfloat162*)(smem + hi_off + s + 4) = h1;
    *(__nv_bfloat162*)(smem + lo_off + s)     = l0;
    *(__nv_bfloat162*)(smem + lo_off + s + 4) = l1;
}

// ===========================================================================
// Projection GEMM (FFMA): g_kvq[b][l][o] = W[o][:] . queries[b][:][l]
// ===========================================================================
__global__ __launch_bounds__(256) void proj_kernel(
    const float* __restrict__ qin,
    const float* __restrict__ w_mem,
    const float* __restrict__ w_q)
{
    __shared__ float As[8][128];
    __shared__ float Bs[8][128];

    const int b  = blockIdx.z;
    const int l0 = blockIdx.x * 128;
    const int o0 = blockIdx.y * 128;
    const int t  = threadIdx.x;
    const int ty = t >> 4, tx = t & 15;

    const float* wptr = (o0 < 1024) ? (w_mem + (size_t)o0 * DD)
                                    : (w_q  + (size_t)(o0 - 1024) * DD);
    const float* qb = qin + (size_t)b * DD * LL;

    float c[8][8];
    #pragma unroll
    for (int i = 0; i < 8; i++)
        #pragma unroll
        for (int j = 0; j < 8; j++) c[i][j] = 0.f;

    const int ak = t >> 5, am = (t & 31) << 2;
    const int bn = t >> 1, bk = (t & 1) << 2;

    for (int d0 = 0; d0 < DD; d0 += 8) {
        float4 av = *(const float4*)(qb + (size_t)(d0 + ak) * LL + l0 + am);
        float4 bv = *(const float4*)(wptr + (size_t)bn * DD + d0 + bk);
        __syncthreads();
        *(float4*)&As[ak][am] = av;
        Bs[bk + 0][bn] = bv.x;
        Bs[bk + 1][bn] = bv.y;
        Bs[bk + 2][bn] = bv.z;
        Bs[bk + 3][bn] = bv.w;
        __syncthreads();
        #pragma unroll
        for (int kk = 0; kk < 8; kk++) {
            float a[8], bb2[8];
            *(float4*)&a[0]   = *(float4*)&As[kk][ty * 8];
            *(float4*)&a[4]   = *(float4*)&As[kk][ty * 8 + 4];
            *(float4*)&bb2[0] = *(float4*)&Bs[kk][tx * 8];
            *(float4*)&bb2[4] = *(float4*)&Bs[kk][tx * 8 + 4];
            #pragma unroll
            for (int i = 0; i < 8; i++)
                #pragma unroll
                for (int j = 0; j < 8; j++)
                    c[i][j] += a[i] * bb2[j];
        }
    }

    const float scale = (o0 >= 1024) ? 0.125f : 1.0f;
    float* outp = g_kvq + (size_t)b * LL * OT;
    #pragma unroll
    for (int i = 0; i < 8; i++) {
        size_t row = (size_t)(l0 + ty * 8 + i) * OT + o0 + tx * 8;
        float4 v0 = make_float4(c[i][0] * scale, c[i][1] * scale,
                                c[i][2] * scale, c[i][3] * scale);
        float4 v1 = make_float4(c[i][4] * scale, c[i][5] * scale,
                                c[i][6] * scale, c[i][7] * scale);
        *(float4*)(outp + row)     = v0;
        *(float4*)(outp + row + 4) = v1;
    }
}

// ===========================================================================
// V transpose: g_vt[b][o][l] = g_kvq[b][l][512+o]
// ===========================================================================
__global__ void vt_kernel() {
    __shared__ float t[32][33];
    const int b  = blockIdx.z;
    const int l0 = blockIdx.x * 32;
    const int o0 = blockIdx.y * 32;
    const int tx = threadIdx.x, ty = threadIdx.y;   // (32, 8)

    #pragma unroll
    for (int i = 0; i < 4; i++) {
        int r = ty + i * 8;
        t[r][tx] = g_kvq[((size_t)b * LL + l0 + r) * OT + 512 + o0 + tx];
    }
    __syncthreads();
    #pragma unroll
    for (int i = 0; i < 4; i++) {
        int r = ty + i * 8;
        g_vt[((size_t)b * DD + o0 + r) * LL + l0 + tx] = t[tx][r];
    }
}

// ===========================================================================
// mma.sync flash attention: block = (b, h, 128 q-rows), 8 warps, warp owns
// 16 q-rows. bf16 hi/lo 3-MMA split ~ fp32 accuracy. No online max:
//   p = mask ? exp(s) : 0 ; O accumulates in registers across all 32 k-tiles.
// ===========================================================================

// smem byte offsets (tiles have 128B rows, SW128-swizzled)
#define SM_QHI  0
#define SM_QLO  (SM_QHI + 16384)
#define SM_KHI  (SM_QLO + 16384)
#define SM_KLO  (SM_KHI + 8192)
#define SM_VHI  (SM_KLO + 8192)
#define SM_VLO  (SM_VHI + 8192)
#define SM_MSK  (SM_VLO + 8192)
#define SM_TOTAL (SM_MSK + 256)
// epilogue reuses [0 .. 128*66*4) as fp32 O tile

__global__ __launch_bounds__(256, 2) void attn_mma(
    const int* __restrict__ mask, float* __restrict__ out)
{
    extern __shared__ char smem[];
    const uint32_t sb = smem_u32(smem);
    const int tid  = threadIdx.x;
    const int w    = tid >> 5;
    const int lane = tid & 31;
    const int b = blockIdx.z, h = blockIdx.y, q0 = blockIdx.x * 128;

    // ---- stage Q tile [128 q][64 dh] as bf16 hi/lo ----
    const float* Qg = g_kvq + ((size_t)b * LL + q0) * OT + 1024 + h * 64;
    #pragma unroll
    for (int i = tid; i < 128 * 16; i += 256) {
        int row = i >> 4, c4 = (i & 15) << 2;
        float4 v = *(const float4*)(Qg + (size_t)row * OT + c4);
        cvt_store4(smem, SM_QHI, SM_QLO, (uint32_t)(row * 128 + c4 * 2), v);
    }

    const float* Kg = g_kvq + (size_t)b * LL * OT + h * 64;
    const float* Vg = g_vt  + ((size_t)b * DD + h * 64) * LL;

    // ldmatrix per-lane geometry (x4: matrix idx = lane>>3, row = lane&7)
    const int mi = lane >> 3;
    const int qrow_l = w * 16 + ((mi & 1) << 3) + (lane & 7);  // A: m0k0,m8k0,m0k8,m8k8
    const int a_colh = (mi >> 1) * 16;                          // k-half byte offset
    const int b_rsub = ((mi >> 1) << 3) + (lane & 7);           // B: (nt j,k0)(j,k8)(j+1,k0)(j+1,k8)
    const int b_colh = (mi & 1) * 16;

    float o_acc[8][4];
    #pragma unroll
    for (int i = 0; i < 8; i++)
        #pragma unroll
        for (int j = 0; j < 4; j++) o_acc[i][j] = 0.f;
    float lsum0 = 0.f, lsum1 = 0.f;

    for (int it = 0; it < 32; it++) {
        const int k0 = it * 64;
        __syncthreads();   // Q staged (it=0) / prev-iter smem reads done

        // ---- stage K [64 key][64 dh] and Vt [64 dh][64 key] hi/lo ----
        #pragma unroll
        for (int i = tid; i < 64 * 16; i += 256) {
            int row = i >> 4, c4 = (i & 15) << 2;
            float4 kv = *(const float4*)(Kg + (size_t)(k0 + row) * OT + c4);
            cvt_store4(smem, SM_KHI, SM_KLO, (uint32_t)(row * 128 + c4 * 2), kv);
            float4 vv = *(const float4*)(Vg + (size_t)row * LL + k0 + c4);
            cvt_store4(smem, SM_VHI, SM_VLO, (uint32_t)(row * 128 + c4 * 2), vv);
        }
        if (tid < 64) ((int*)(smem + SM_MSK))[tid] = mask[(size_t)b * LL + k0 + tid];
        __syncthreads();

        // ---- S = Q.K^T : s[nt][4], nt over 8 key-octets ----
        float s[8][4];
        #pragma unroll
        for (int i = 0; i < 8; i++)
            #pragma unroll
            for (int j = 0; j < 4; j++) s[i][j] = 0.f;

        #pragma unroll
        for (int kc = 0; kc < 4; kc++) {
            uint32_t ahi[4], alo[4];
            uint32_t qoff = (uint32_t)(qrow_l * 128 + kc * 32 + a_colh);
            ldsm4(ahi, sb + SM_QHI + SWZ128(qoff));
            ldsm4(alo, sb + SM_QLO + SWZ128(qoff));
            #pragma unroll
            for (int j = 0; j < 8; j += 2) {
                uint32_t bhi[4], blo[4];
                uint32_t koff = (uint32_t)((j * 8 + b_rsub) * 128 + kc * 32 + b_colh);
                ldsm4(bhi, sb + SM_KHI + SWZ128(koff));
                ldsm4(blo, sb + SM_KLO + SWZ128(koff));
                mma16816(s[j],     ahi, bhi);
                mma16816(s[j],     ahi, blo);
                mma16816(s[j],     alo, bhi);
                mma16816(s[j + 1], ahi, bhi + 2);
                mma16816(s[j + 1], ahi, blo + 2);
                mma16816(s[j + 1], alo, bhi + 2);
            }
        }

        // ---- softmax (no max-sub), pack P as bf16 hi/lo A-fragments ----
        uint32_t phiA[8], phiB[8], ploA[8], ploB[8];
        const int* mp = (const int*)(smem + SM_MSK);
        #pragma unroll
        for (int nt = 0; nt < 8; nt++) {
            const int c0 = nt * 8 + ((lane & 3) << 1);
            const bool m0v = mp[c0] != 0, m1v = mp[c0 + 1] != 0;
            float p0 = m0v ? __expf(s[nt][0]) : 0.f;
            float p1 = m1v ? __expf(s[nt][1]) : 0.f;
            float p2 = m0v ? __expf(s[nt][2]) : 0.f;
            float p3 = m1v ? __expf(s[nt][3]) : 0.f;
            lsum0 += p0 + p1;
            lsum1 += p2 + p3;
            __nv_bfloat162 hA, hB, lA, lB;
            hA.x = __float2bfloat16_rn(p0); hA.y = __float2bfloat16_rn(p1);
            hB.x = __float2bfloat16_rn(p2); hB.y = __float2bfloat16_rn(p3);
            lA.x = __float2bfloat16_rn(p0 - __bfloat162float(hA.x));
            lA.y = __float2bfloat16_rn(p1 - __bfloat162float(hA.y));
            lB.x = __float2bfloat16_rn(p2 - __bfloat162float(hB.x));
            lB.y = __float2bfloat16_rn(p3 - __bfloat162float(hB.y));
            phiA[nt] = *(uint32_t*)&hA; phiB[nt] = *(uint32_t*)&hB;
            ploA[nt] = *(uint32_t*)&lA; ploB[nt] = *(uint32_t*)&lB;
        }

        // ---- O += P.V ----
        #pragma unroll
        for (int kc = 0; kc < 4; kc++) {
            uint32_t ahi[4] = {phiA[2 * kc], phiB[2 * kc], phiA[2 * kc + 1], phiB[2 * kc + 1]};
            uint32_t alo[4] = {ploA[2 * kc], ploB[2 * kc], ploA[2 * kc + 1], ploB[2 * kc + 1]};
            #pragma unroll
            for (int j = 0; j < 8; j += 2) {
                uint32_t bhi[4], blo[4];
                uint32_t voff = (uint32_t)((j * 8 + b_rsub) * 128 + kc * 32 + b_colh);
                ldsm4(bhi, sb + SM_VHI + SWZ128(voff));
                ldsm4(blo, sb + SM_VLO + SWZ128(voff));
                mma16816(o_acc[j],     ahi, bhi);
                mma16816(o_acc[j],     ahi, blo);
                mma16816(o_acc[j],     alo, bhi);
                mma16816(o_acc[j + 1], ahi, bhi + 2);
                mma16816(o_acc[j + 1], ahi, blo + 2);
                mma16816(o_acc[j + 1], alo, bhi + 2);
            }
        }
    }

    // ---- final row-sum reduce (lanes 4r..4r+3 share a row) & normalize ----
    #pragma unroll
    for (int off = 1; off < 4; off <<= 1) {
        lsum0 += __shfl_xor_sync(0xffffffffu, lsum0, off);
        lsum1 += __shfl_xor_sync(0xffffffffu, lsum1, off);
    }
    const float inv0 = 1.0f / lsum0, inv1 = 1.0f / lsum1;

    // ---- stage normalized O to smem [q][66], then coalesced store ----
    __syncthreads();
    float* Osm = (float*)smem;
    const int r1 = w * 16 + (lane >> 2);
    const int cb = (lane & 3) << 1;
    #pragma unroll
    for (int nt = 0; nt < 8; nt++) {
        const int c0 = nt * 8 + cb;
        Osm[r1 * 66 + c0]           = o_acc[nt][0] * inv0;
        Osm[r1 * 66 + c0 + 1]       = o_acc[nt][1] * inv0;
        Osm[(r1 + 8) * 66 + c0]     = o_acc[nt][2] * inv1;
        Osm[(r1 + 8) * 66 + c0 + 1] = o_acc[nt][3] * inv1;
    }
    __syncthreads();
    {
        const int dh = tid >> 2;
        const int qc = (tid & 3) << 5;
        float* op = out + ((size_t)b * DD + h * 64 + dh) * LL + q0 + qc;
        #pragma unroll
        for (int i = 0; i < 8; i++) {
            float4 v = make_float4(Osm[(qc + 4 * i + 0) * 66 + dh],
                                   Osm[(qc + 4 * i + 1) * 66 + dh],
                                   Osm[(qc + 4 * i + 2) * 66 + dh],
                                   Osm[(qc + 4 * i + 3) * 66 + dh]);
            *(float4*)(op + 4 * i) = v;
        }
    }
}

// ===========================================================================
extern "C" void kernel_launch(void* const* d_in, const int* in_sizes, int n_in,
                              void* d_out, int out_size) {
    (void)in_sizes; (void)n_in; (void)out_size;
    const float* queries = (const float*)d_in[0];
    const int*   mask    = (const int*)d_in[1];
    const float* w_mem   = (const float*)d_in[2];
    const float* w_q     = (const float*)d_in[3];
    float* out = (float*)d_out;

    dim3 gp(LL / 128, OT / 128, BB);
    proj_kernel<<<gp, 256>>>(queries, w_mem, w_q);

    dim3 gt(LL / 32, DD / 32, BB);
    vt_kernel<<<gt, dim3(32, 8)>>>();

    cudaFuncSetAttribute(attn_mma, cudaFuncAttributeMaxDynamicSharedMemorySize, SM_TOTAL);
    dim3 ga(LL / 128, HH, BB);   // 16 x 8 x 8 = 1024 blocks
    attn_mma<<<ga, 256, SM_TOTAL>>>(mask, out);
}

// round 6
// speedup vs baseline: 4.8792x; 1.4567x over previous
#include <cuda_runtime.h>
#include <cuda_bf16.h>
#include <cstdint>
#include <math.h>

#define BB 8
#define DD 512
#define LL 2048
#define HH 8
#define OT 1536        // fused proj cols: [0,512)=K, [512,1024)=V(unused), [1024,1536)=Q(scaled)

// fp32 scratch: K/Q in [l][o] layout (g_kvq) + V in [o][l] layout (g_vt)
__device__ float g_kvq[(size_t)BB * LL * OT];
__device__ float g_vt[(size_t)BB * DD * LL];

// ============================ helpers ======================================
__device__ __forceinline__ uint32_t smem_u32(const void* p) {
    uint32_t a;
    asm("{ .reg .u64 t; cvta.to.shared.u64 t, %1; cvt.u32.u64 %0, t; }"
        : "=r"(a) : "l"(p));
    return a;
}

#define SWZ128(off) ((off) ^ (((off) >> 3) & 0x70))

__device__ __forceinline__ void ldsm4(uint32_t* r, uint32_t addr) {
    asm volatile("ldmatrix.sync.aligned.m8n8.x4.shared.b16 {%0,%1,%2,%3}, [%4];"
        : "=r"(r[0]), "=r"(r[1]), "=r"(r[2]), "=r"(r[3]) : "r"(addr));
}

__device__ __forceinline__ void ldsm4t(uint32_t* r, uint32_t addr) {
    asm volatile("ldmatrix.sync.aligned.m8n8.x4.trans.shared.b16 {%0,%1,%2,%3}, [%4];"
        : "=r"(r[0]), "=r"(r[1]), "=r"(r[2]), "=r"(r[3]) : "r"(addr));
}

__device__ __forceinline__ void mma16816(float* d, const uint32_t* a, const uint32_t* b) {
    asm volatile("mma.sync.aligned.m16n8k16.row.col.f32.bf16.bf16.f32 "
        "{%0,%1,%2,%3}, {%4,%5,%6,%7}, {%8,%9}, {%0,%1,%2,%3};"
        : "+f"(d[0]), "+f"(d[1]), "+f"(d[2]), "+f"(d[3])
        : "r"(a[0]), "r"(a[1]), "r"(a[2]), "r"(a[3]), "r"(b[0]), "r"(b[1]));
}

// split fp32x4 -> bf16 hi/lo pairs, store swizzled (byte_off within tile)
__device__ __forceinline__ void cvt_store4(char* smem, uint32_t hi_off, uint32_t lo_off,
                                           uint32_t byte_off, float4 v) {
    __nv_bfloat162 h0, h1, l0, l1;
    h0.x = __float2bfloat16_rn(v.x); h0.y = __float2bfloat16_rn(v.y);
    h1.x = __float2bfloat16_rn(v.z); h1.y = __float2bfloat16_rn(v.w);
    l0.x = __float2bfloat16_rn(v.x - __bfloat162float(h0.x));
    l0.y = __float2bfloat16_rn(v.y - __bfloat162float(h0.y));
    l1.x = __float2bfloat16_rn(v.z - __bfloat162float(h1.x));
    l1.y = __float2bfloat16_rn(v.w - __bfloat162float(h1.y));
    uint32_t s = SWZ128(byte_off);
    *(__nv_bfloat162*)(smem + hi_off + s)     = h0;
    *(__nv_bfloat162*)(smem + hi_off + s + 4) = h1;
    *(__nv_bfloat162*)(smem + lo_off + s)     = l0;
    *(__nv_bfloat162*)(smem + lo_off + s + 4) = l1;
}

// ===========================================================================
// Projection GEMM on tensor pipe:
//   out2[o][l] = sum_d W[o][d] * q[d][l]   (per batch)
// A = W rows [o][d] (k-contiguous), B = q tile [d][l] via ldmatrix.trans.
// Epilogue: V blocks -> g_vt[o][l] direct; K/Q blocks -> g_kvq[l][o] transposed.
// ===========================================================================
#define PA_HI  0
#define PA_LO  16384
#define PB0_HI 32768
#define PB0_LO 40960
#define PB1_HI 49152
#define PB1_LO 57344
#define OSTRIDE 132            // fp32 epilogue row stride: 132*4=528B, 16B-aligned rows
#define P_TOTAL (128 * OSTRIDE * 4)   // 67584 >= 65536 staging

__global__ __launch_bounds__(256, 2) void proj_mma(
    const float* __restrict__ qin,
    const float* __restrict__ w_mem,
    const float* __restrict__ w_q)
{
    extern __shared__ char smem[];
    const uint32_t sb = smem_u32(smem);
    const int tid = threadIdx.x;
    const int w = tid >> 5, lane = tid & 31;
    const int b  = blockIdx.z;
    const int l0 = blockIdx.x * 128;
    const int o0 = blockIdx.y * 128;

    const float* wptr = (o0 < 1024) ? (w_mem + (size_t)o0 * DD)
                                    : (w_q  + (size_t)(o0 - 1024) * DD);
    const float* qb = qin + (size_t)b * DD * LL;

    // per-lane ldmatrix geometry
    const int mi     = lane >> 3;
    const int arow   = w * 16 + ((mi & 1) << 3) + (lane & 7);  // A: m0k0,m8k0,m0k8,m8k8
    const int acolh  = (mi >> 1) * 16;
    const int b_ksub = ((mi & 1) << 3) + (lane & 7);           // B(trans): k rows
    const int b_noct = mi >> 1;                                 // octet sub-select

    float c[16][4];
    #pragma unroll
    for (int i = 0; i < 16; i++)
        #pragma unroll
        for (int j = 0; j < 4; j++) c[i][j] = 0.f;

    for (int kc = 0; kc < 8; kc++) {
        __syncthreads();
        // stage A: W[o0..+128][kc*64..+64] -> [o][d] 128B rows
        #pragma unroll
        for (int i = tid; i < 128 * 16; i += 256) {
            int row = i >> 4, d4 = (i & 15) << 2;
            float4 v = *(const float4*)(wptr + (size_t)row * DD + kc * 64 + d4);
            cvt_store4(smem, PA_HI, PA_LO, (uint32_t)(row * 128 + d4 * 2), v);
        }
        // stage B: q[kc*64..+64][l0..+128] -> two [d][64 l] half tiles
        #pragma unroll
        for (int i = tid; i < 64 * 32; i += 256) {
            int row = i >> 5, l4 = (i & 31) << 2;
            float4 v = *(const float4*)(qb + (size_t)(kc * 64 + row) * LL + l0 + l4);
            uint32_t hi = (l4 & 64) ? PB1_HI : PB0_HI;
            uint32_t lo = (l4 & 64) ? PB1_LO : PB0_LO;
            cvt_store4(smem, hi, lo, (uint32_t)(row * 128 + (l4 & 63) * 2), v);
        }
        __syncthreads();

        #pragma unroll
        for (int ks = 0; ks < 4; ks++) {
            uint32_t ahi[4], alo[4];
            uint32_t aoff = (uint32_t)(arow * 128 + ks * 32 + acolh);
            ldsm4(ahi, sb + PA_HI + SWZ128(aoff));
            ldsm4(alo, sb + PA_LO + SWZ128(aoff));
            #pragma unroll
            for (int hb = 0; hb < 2; hb++) {
                const uint32_t bh = sb + (hb ? PB1_HI : PB0_HI);
                const uint32_t bl = sb + (hb ? PB1_LO : PB0_LO);
                #pragma unroll
                for (int j = 0; j < 8; j += 2) {
                    uint32_t boff = (uint32_t)((ks * 16 + b_ksub) * 128 + (j + b_noct) * 16);
                    uint32_t bhi[4], blo[4];
                    ldsm4t(bhi, bh + SWZ128(boff));
                    ldsm4t(blo, bl + SWZ128(boff));
                    const int o1 = hb * 8 + j;
                    mma16816(c[o1],     ahi, bhi);
                    mma16816(c[o1],     ahi, blo);
                    mma16816(c[o1],     alo, bhi);
                    mma16816(c[o1 + 1], ahi, bhi + 2);
                    mma16816(c[o1 + 1], ahi, blo + 2);
                    mma16816(c[o1 + 1], alo, bhi + 2);
                }
            }
        }
    }

    // ---- epilogue: fragments -> smem [o][OSTRIDE] fp32 ----
    __syncthreads();
    float* Osm = (float*)smem;
    {
        const int r1 = w * 16 + (lane >> 2);
        const int cb = (lane & 3) << 1;
        #pragma unroll
        for (int oct = 0; oct < 16; oct++) {
            const int col = (oct >> 3) * 64 + (oct & 7) * 8 + cb;
            Osm[r1 * OSTRIDE + col]           = c[oct][0];
            Osm[r1 * OSTRIDE + col + 1]       = c[oct][1];
            Osm[(r1 + 8) * OSTRIDE + col]     = c[oct][2];
            Osm[(r1 + 8) * OSTRIDE + col + 1] = c[oct][3];
        }
    }
    __syncthreads();

    if (o0 >= 512 && o0 < 1024) {
        // V block: direct [o][l] rows into g_vt
        float* vp = g_vt + ((size_t)b * DD + (o0 - 512)) * LL + l0;
        #pragma unroll
        for (int i = tid; i < 128 * 32; i += 256) {
            int row = i >> 5, l4 = (i & 31) << 2;
            *(float4*)(vp + (size_t)row * LL + l4) = *(float4*)&Osm[row * OSTRIDE + l4];
        }
    } else {
        // K/Q block: transposed [l][o] float4 stores into g_kvq
        const float sc = (o0 >= 1024) ? 0.125f : 1.0f;
        const int c32 = tid & 31, lr = tid >> 5;
        #pragma unroll
        for (int i = 0; i < 16; i++) {
            const int l = lr + i * 8;
            float4 v;
            v.x = Osm[(c32 * 4 + 0) * OSTRIDE + l] * sc;
            v.y = Osm[(c32 * 4 + 1) * OSTRIDE + l] * sc;
            v.z = Osm[(c32 * 4 + 2) * OSTRIDE + l] * sc;
            v.w = Osm[(c32 * 4 + 3) * OSTRIDE + l] * sc;
            *(float4*)&g_kvq[((size_t)b * LL + l0 + l) * OT + o0 + c32 * 4] = v;
        }
    }
}

// ===========================================================================
// mma.sync flash attention (unchanged, validated in Round 4)
// ===========================================================================
#define SM_QHI  0
#define SM_QLO  (SM_QHI + 16384)
#define SM_KHI  (SM_QLO + 16384)
#define SM_KLO  (SM_KHI + 8192)
#define SM_VHI  (SM_KLO + 8192)
#define SM_VLO  (SM_VHI + 8192)
#define SM_MSK  (SM_VLO + 8192)
#define SM_TOTAL (SM_MSK + 256)

__global__ __launch_bounds__(256, 2) void attn_mma(
    const int* __restrict__ mask, float* __restrict__ out)
{
    extern __shared__ char smem[];
    const uint32_t sb = smem_u32(smem);
    const int tid  = threadIdx.x;
    const int w    = tid >> 5;
    const int lane = tid & 31;
    const int b = blockIdx.z, h = blockIdx.y, q0 = blockIdx.x * 128;

    const float* Qg = g_kvq + ((size_t)b * LL + q0) * OT + 1024 + h * 64;
    #pragma unroll
    for (int i = tid; i < 128 * 16; i += 256) {
        int row = i >> 4, c4 = (i & 15) << 2;
        float4 v = *(const float4*)(Qg + (size_t)row * OT + c4);
        cvt_store4(smem, SM_QHI, SM_QLO, (uint32_t)(row * 128 + c4 * 2), v);
    }

    const float* Kg = g_kvq + (size_t)b * LL * OT + h * 64;
    const float* Vg = g_vt  + ((size_t)b * DD + h * 64) * LL;

    const int mi = lane >> 3;
    const int qrow_l = w * 16 + ((mi & 1) << 3) + (lane & 7);
    const int a_colh = (mi >> 1) * 16;
    const int b_rsub = ((mi >> 1) << 3) + (lane & 7);
    const int b_colh = (mi & 1) * 16;

    float o_acc[8][4];
    #pragma unroll
    for (int i = 0; i < 8; i++)
        #pragma unroll
        for (int j = 0; j < 4; j++) o_acc[i][j] = 0.f;
    float lsum0 = 0.f, lsum1 = 0.f;

    for (int it = 0; it < 32; it++) {
        const int k0 = it * 64;
        __syncthreads();

        #pragma unroll
        for (int i = tid; i < 64 * 16; i += 256) {
            int row = i >> 4, c4 = (i & 15) << 2;
            float4 kv = *(const float4*)(Kg + (size_t)(k0 + row) * OT + c4);
            cvt_store4(smem, SM_KHI, SM_KLO, (uint32_t)(row * 128 + c4 * 2), kv);
            float4 vv = *(const float4*)(Vg + (size_t)row * LL + k0 + c4);
            cvt_store4(smem, SM_VHI, SM_VLO, (uint32_t)(row * 128 + c4 * 2), vv);
        }
        if (tid < 64) ((int*)(smem + SM_MSK))[tid] = mask[(size_t)b * LL + k0 + tid];
        __syncthreads();

        float s[8][4];
        #pragma unroll
        for (int i = 0; i < 8; i++)
            #pragma unroll
            for (int j = 0; j < 4; j++) s[i][j] = 0.f;

        #pragma unroll
        for (int kc = 0; kc < 4; kc++) {
            uint32_t ahi[4], alo[4];
            uint32_t qoff = (uint32_t)(qrow_l * 128 + kc * 32 + a_colh);
            ldsm4(ahi, sb + SM_QHI + SWZ128(qoff));
            ldsm4(alo, sb + SM_QLO + SWZ128(qoff));
            #pragma unroll
            for (int j = 0; j < 8; j += 2) {
                uint32_t bhi[4], blo[4];
                uint32_t koff = (uint32_t)((j * 8 + b_rsub) * 128 + kc * 32 + b_colh);
                ldsm4(bhi, sb + SM_KHI + SWZ128(koff));
                ldsm4(blo, sb + SM_KLO + SWZ128(koff));
                mma16816(s[j],     ahi, bhi);
                mma16816(s[j],     ahi, blo);
                mma16816(s[j],     alo, bhi);
                mma16816(s[j + 1], ahi, bhi + 2);
                mma16816(s[j + 1], ahi, blo + 2);
                mma16816(s[j + 1], alo, bhi + 2);
            }
        }

        uint32_t phiA[8], phiB[8], ploA[8], ploB[8];
        const int* mp = (const int*)(smem + SM_MSK);
        #pragma unroll
        for (int nt = 0; nt < 8; nt++) {
            const int c0 = nt * 8 + ((lane & 3) << 1);
            const bool m0v = mp[c0] != 0, m1v = mp[c0 + 1] != 0;
            float p0 = m0v ? __expf(s[nt][0]) : 0.f;
            float p1 = m1v ? __expf(s[nt][1]) : 0.f;
            float p2 = m0v ? __expf(s[nt][2]) : 0.f;
            float p3 = m1v ? __expf(s[nt][3]) : 0.f;
            lsum0 += p0 + p1;
            lsum1 += p2 + p3;
            __nv_bfloat162 hA, hB, lA, lB;
            hA.x = __float2bfloat16_rn(p0); hA.y = __float2bfloat16_rn(p1);
            hB.x = __float2bfloat16_rn(p2); hB.y = __float2bfloat16_rn(p3);
            lA.x = __float2bfloat16_rn(p0 - __bfloat162float(hA.x));
            lA.y = __float2bfloat16_rn(p1 - __bfloat162float(hA.y));
            lB.x = __float2bfloat16_rn(p2 - __bfloat162float(hB.x));
            lB.y = __float2bfloat16_rn(p3 - __bfloat162float(hB.y));
            phiA[nt] = *(uint32_t*)&hA; phiB[nt] = *(uint32_t*)&hB;
            ploA[nt] = *(uint32_t*)&lA; ploB[nt] = *(uint32_t*)&lB;
        }

        #pragma unroll
        for (int kc = 0; kc < 4; kc++) {
            uint32_t ahi[4] = {phiA[2 * kc], phiB[2 * kc], phiA[2 * kc + 1], phiB[2 * kc + 1]};
            uint32_t alo[4] = {ploA[2 * kc], ploB[2 * kc], ploA[2 * kc + 1], ploB[2 * kc + 1]};
            #pragma unroll
            for (int j = 0; j < 8; j += 2) {
                uint32_t bhi[4], blo[4];
                uint32_t voff = (uint32_t)((j * 8 + b_rsub) * 128 + kc * 32 + b_colh);
                ldsm4(bhi, sb + SM_VHI + SWZ128(voff));
                ldsm4(blo, sb + SM_VLO + SWZ128(voff));
                mma16816(o_acc[j],     ahi, bhi);
                mma16816(o_acc[j],     ahi, blo);
                mma16816(o_acc[j],     alo, bhi);
                mma16816(o_acc[j + 1], ahi, bhi + 2);
                mma16816(o_acc[j + 1], ahi, blo + 2);
                mma16816(o_acc[j + 1], alo, bhi + 2);
            }
        }
    }

    #pragma unroll
    for (int off = 1; off < 4; off <<= 1) {
        lsum0 += __shfl_xor_sync(0xffffffffu, lsum0, off);
        lsum1 += __shfl_xor_sync(0xffffffffu, lsum1, off);
    }
    const float inv0 = 1.0f / lsum0, inv1 = 1.0f / lsum1;

    __syncthreads();
    float* Osm = (float*)smem;
    const int r1 = w * 16 + (lane >> 2);
    const int cb = (lane & 3) << 1;
    #pragma unroll
    for (int nt = 0; nt < 8; nt++) {
        const int c0 = nt * 8 + cb;
        Osm[r1 * 66 + c0]           = o_acc[nt][0] * inv0;
        Osm[r1 * 66 + c0 + 1]       = o_acc[nt][1] * inv0;
        Osm[(r1 + 8) * 66 + c0]     = o_acc[nt][2] * inv1;
        Osm[(r1 + 8) * 66 + c0 + 1] = o_acc[nt][3] * inv1;
    }
    __syncthreads();
    {
        const int dh = tid >> 2;
        const int qc = (tid & 3) << 5;
        float* op = out + ((size_t)b * DD + h * 64 + dh) * LL + q0 + qc;
        #pragma unroll
        for (int i = 0; i < 8; i++) {
            float4 v = make_float4(Osm[(qc + 4 * i + 0) * 66 + dh],
                                   Osm[(qc + 4 * i + 1) * 66 + dh],
                                   Osm[(qc + 4 * i + 2) * 66 + dh],
                                   Osm[(qc + 4 * i + 3) * 66 + dh]);
            *(float4*)(op + 4 * i) = v;
        }
    }
}

// ===========================================================================
extern "C" void kernel_launch(void* const* d_in, const int* in_sizes, int n_in,
                              void* d_out, int out_size) {
    (void)in_sizes; (void)n_in; (void)out_size;
    const float* queries = (const float*)d_in[0];
    const int*   mask    = (const int*)d_in[1];
    const float* w_mem   = (const float*)d_in[2];
    const float* w_q     = (const float*)d_in[3];
    float* out = (float*)d_out;

    cudaFuncSetAttribute(proj_mma, cudaFuncAttributeMaxDynamicSharedMemorySize, P_TOTAL);
    dim3 gp(LL / 128, OT / 128, BB);          // 16 x 12 x 8 = 1536 blocks
    proj_mma<<<gp, 256, P_TOTAL>>>(queries, w_mem, w_q);

    cudaFuncSetAttribute(attn_mma, cudaFuncAttributeMaxDynamicSharedMemorySize, SM_TOTAL);
    dim3 ga(LL / 128, HH, BB);                // 16 x 8 x 8 = 1024 blocks
    attn_mma<<<ga, 256, SM_TOTAL>>>(mask, out);
}